// round 13
// baseline (speedup 1.0000x reference)
#include <cuda_runtime.h>
#include <cstdint>
#include <cstddef>

// VQ via legacy warp-level mma.sync (tf32, 3-split), pre-split packed codebook,
// cp.async double-buffered pipeline. dist_j = ||c_j||^2 - 2 x.c_j.

#define N_PTS    16384
#define DIMS     64
#define K_CODES  8192
#define TM       128               // points per CTA
#define TK       128               // codes per tile
#define NTILES   (K_CODES / TK)    // 64
#define NTHREADS 256

#define SM_CSQ 0                   // 2 x 512 B (double-buffered csq)
#define SM_IDX 1024                // 512 B
#define SM_B   2048                // 2 x 64 KB packed fragment buffers
#define SM_BUF 65536
#define SMEM_BYTES (SM_B + 2 * SM_BUF)   // 133120

__device__ __align__(16) float g_csq[K_CODES];
// packed: [tile][ntile 16][kk 8][lane 32] -> uint4 {bh0, bh1, bl0, bl1}
__device__ uint4 g_cbp[NTILES * 16 * 8 * 32];   // 4 MB

// ---- tf32 split ----
__device__ __forceinline__ void tf32_split(float x, uint32_t& hi, uint32_t& lo) {
    uint32_t h, l;
    asm("cvt.rna.tf32.f32 %0, %1;" : "=r"(h) : "f"(x));
    float r = x - __uint_as_float(h);
    asm("cvt.rna.tf32.f32 %0, %1;" : "=r"(l) : "f"(r));
    hi = h; lo = l;
}

// ---- csq precompute (exact fp32) ----
__global__ void __launch_bounds__(256) csq_kernel(const float* __restrict__ cb) {
    int i = blockIdx.x * blockDim.x + threadIdx.x;
    if (i >= K_CODES) return;
    const float4* row = reinterpret_cast<const float4*>(cb + (size_t)i * DIMS);
    float s = 0.f;
#pragma unroll
    for (int q = 0; q < DIMS / 4; q++) {
        float4 v = row[q];
        s += v.x * v.x + v.y * v.y + v.z * v.z + v.w * v.w;
    }
    g_csq[i] = s;
}

// ---- pack codebook into fragment-ordered tf32 hi/lo quads ----
__global__ void __launch_bounds__(256) pack_kernel(const float* __restrict__ cb) {
    int idx = blockIdx.x * 256 + threadIdx.x;   // 262144 quads
    int lane = idx & 31;
    int kk   = (idx >> 5) & 7;
    int nt   = (idx >> 8) & 15;
    int t    = idx >> 12;
    int code = t * TK + nt * 8 + (lane >> 2);
    int k0   = kk * 8 + (lane & 3);
    float x0 = cb[(size_t)code * DIMS + k0];
    float x1 = cb[(size_t)code * DIMS + k0 + 4];
    uint4 v;
    tf32_split(x0, v.x, v.z);
    tf32_split(x1, v.y, v.w);
    g_cbp[idx] = v;
}

// ---- PTX helpers -------------------------------------------------------------
__device__ __forceinline__ uint32_t smem_u32(const void* p) {
    uint32_t a;
    asm("{ .reg .u64 t; cvta.to.shared.u64 t, %1; cvt.u32.u64 %0, t; }" : "=r"(a) : "l"(p));
    return a;
}
__device__ __forceinline__ void cp16(uint32_t dst, const void* src) {
    asm volatile("cp.async.cg.shared.global [%0], [%1], 16;" :: "r"(dst), "l"(src));
}
#define CP_COMMIT() asm volatile("cp.async.commit_group;" ::: "memory")
#define CP_WAIT1()  asm volatile("cp.async.wait_group 1;" ::: "memory")
#define CP_WAIT0()  asm volatile("cp.async.wait_group 0;" ::: "memory")

__device__ __forceinline__ void mma8(float d[4], const uint32_t a[4],
                                     uint32_t b0, uint32_t b1) {
    asm("mma.sync.aligned.m16n8k8.row.col.f32.tf32.tf32.f32 "
        "{%0,%1,%2,%3}, {%4,%5,%6,%7}, {%8,%9}, {%0,%1,%2,%3};"
        : "+f"(d[0]), "+f"(d[1]), "+f"(d[2]), "+f"(d[3])
        : "r"(a[0]), "r"(a[1]), "r"(a[2]), "r"(a[3]), "r"(b0), "r"(b1));
}

// thread copies its 256 B slice of the packed tile + csq (lanes of warp 0)
__device__ __forceinline__ void issue_tile(uint32_t sbase, int t, int buf, int tid) {
    const char* src = reinterpret_cast<const char*>(g_cbp) + (size_t)t * SM_BUF + tid * 256;
    uint32_t dst = sbase + SM_B + buf * SM_BUF + tid * 256;
#pragma unroll
    for (int q = 0; q < 16; q++) cp16(dst + q * 16, src + q * 16);
    if (tid < 32) cp16(sbase + SM_CSQ + buf * 512 + tid * 16, g_csq + t * TK + tid * 4);
}

// ---- main kernel -------------------------------------------------------------
__global__ void __launch_bounds__(NTHREADS, 1) vq_mma_kernel(
    const float* __restrict__ enc,
    const float* __restrict__ cb,
    float* __restrict__ out)
{
    extern __shared__ __align__(128) char smem[];
    const uint32_t sbase = smem_u32(smem);
    float* csq_s = reinterpret_cast<float*>(smem + SM_CSQ);
    int*   sidx  = reinterpret_cast<int*>(smem + SM_IDX);

    const int tid  = threadIdx.x;
    const int lane = tid & 31;
    const int wid  = tid >> 5;
    const int gID  = lane >> 2;
    const int tig  = lane & 3;
    const int pbase = blockIdx.x * TM;

    // kick off tile 0 immediately (overlaps A-fragment setup)
    issue_tile(sbase, 0, 0, tid);
    CP_COMMIT();

    // ---- A fragments: 16 points x 64 dims, tf32 hi/lo, register-resident ----
    uint32_t ah[8][4], al[8][4];
    {
        const float* e0 = enc + (size_t)(pbase + wid * 16 + gID) * DIMS;
        const float* e1 = e0 + 8 * DIMS;
#pragma unroll
        for (int kk = 0; kk < 8; kk++) {
            int k0 = kk * 8 + tig;
            tf32_split(e0[k0],     ah[kk][0], al[kk][0]);
            tf32_split(e1[k0],     ah[kk][1], al[kk][1]);
            tf32_split(e0[k0 + 4], ah[kk][2], al[kk][2]);
            tf32_split(e1[k0 + 4], ah[kk][3], al[kk][3]);
        }
    }

    float bd0 = 3.402823466e38f, bd1 = 3.402823466e38f;
    int   bi0 = 0, bi1 = 0;

#pragma unroll 1
    for (int t = 0; t < NTILES; t++) {
        const int buf = t & 1;
        if (t + 1 < NTILES) {
            issue_tile(sbase, t + 1, buf ^ 1, tid);   // writes other buffer (reads done
            CP_COMMIT();                              //  before last iter's barrier)
            CP_WAIT1();                               // tile t landed
        } else {
            CP_WAIT0();
        }
        __syncthreads();

        const uint32_t fbl = sbase + SM_B + buf * SM_BUF + lane * 16;
        const float* cst = csq_s + buf * 128;

#pragma unroll
        for (int jg = 0; jg < 4; jg++) {
            float dhh[4][4], dco[4][4];
#pragma unroll
            for (int u = 0; u < 4; u++)
#pragma unroll
                for (int e = 0; e < 4; e++) { dhh[u][e] = 0.f; dco[u][e] = 0.f; }

#pragma unroll
            for (int kk = 0; kk < 8; kk++) {
#pragma unroll
                for (int u = 0; u < 4; u++) {
                    uint32_t f0, f1, f2, f3;
                    asm("ld.shared.v4.u32 {%0,%1,%2,%3}, [%4];"
                        : "=r"(f0), "=r"(f1), "=r"(f2), "=r"(f3)
                        : "r"(fbl + ((((jg * 4 + u) * 8 + kk)) << 9)));
                    mma8(dco[u], ah[kk], f2, f3);   // hi_a . lo_b
                    mma8(dco[u], al[kk], f0, f1);   // lo_a . hi_b
                    mma8(dhh[u], ah[kk], f0, f1);   // hi_a . hi_b
                }
            }

            // ---- epilogue: dist = csq - 2*(hh + corr); ascending strict < ----
#pragma unroll
            for (int u = 0; u < 4; u++) {
                const int colb = (jg * 4 + u) * 8 + 2 * tig;
                const int gidx = t * TK + colb;
                const float cs0 = cst[colb], cs1 = cst[colb + 1];
                float e00 = fmaf(-2.f, dhh[u][0] + dco[u][0], cs0);
                float e01 = fmaf(-2.f, dhh[u][1] + dco[u][1], cs1);
                float e10 = fmaf(-2.f, dhh[u][2] + dco[u][2], cs0);
                float e11 = fmaf(-2.f, dhh[u][3] + dco[u][3], cs1);
                if (e00 < bd0) { bd0 = e00; bi0 = gidx; }
                if (e01 < bd0) { bd0 = e01; bi0 = gidx + 1; }
                if (e10 < bd1) { bd1 = e10; bi1 = gidx; }
                if (e11 < bd1) { bd1 = e11; bi1 = gidx + 1; }
            }
        }
        __syncthreads();   // all reads of buf done before next iter overwrites it
    }

    // ---- reduce across the 4 tig lanes (lexicographic: earliest index wins) ----
#pragma unroll
    for (int m = 1; m < 4; m <<= 1) {
        float od0 = __shfl_xor_sync(0xFFFFFFFFu, bd0, m);
        int   oi0 = __shfl_xor_sync(0xFFFFFFFFu, bi0, m);
        float od1 = __shfl_xor_sync(0xFFFFFFFFu, bd1, m);
        int   oi1 = __shfl_xor_sync(0xFFFFFFFFu, bi1, m);
        if (od0 < bd0 || (od0 == bd0 && oi0 < bi0)) { bd0 = od0; bi0 = oi0; }
        if (od1 < bd1 || (od1 == bd1 && oi1 < bi1)) { bd1 = od1; bi1 = oi1; }
    }
    if (tig == 0) {
        sidx[wid * 16 + gID]     = bi0;
        sidx[wid * 16 + gID + 8] = bi1;
    }
    __syncthreads();

    // ---- gather: out[p] = codebook[argmin] (exact fp32 row copy) ----
    {
        const int r = tid >> 1, h = tid & 1;
        const int ci = sidx[r];
        const float4* src = reinterpret_cast<const float4*>(cb + (size_t)ci * DIMS + h * 32);
        float4* dst = reinterpret_cast<float4*>(out + (size_t)(pbase + r) * DIMS + h * 32);
#pragma unroll
        for (int q = 0; q < 8; q++) dst[q] = src[q];
    }
}

// ---- launcher ------------------------------------------------------------------
extern "C" void kernel_launch(void* const* d_in, const int* in_sizes, int n_in,
                              void* d_out, int out_size) {
    const float* enc = (const float*)d_in[0];
    const float* cb  = (const float*)d_in[1];
    float* out = (float*)d_out;

    static bool attr_set = false;
    if (!attr_set) {
        cudaFuncSetAttribute(vq_mma_kernel, cudaFuncAttributeMaxDynamicSharedMemorySize,
                             (int)SMEM_BYTES);
        attr_set = true;
    }

    csq_kernel<<<K_CODES / 256, 256>>>(cb);
    pack_kernel<<<NTILES * 16 * 8 * 32 / 256, 256>>>(cb);
    vq_mma_kernel<<<N_PTS / TM, NTHREADS, SMEM_BYTES>>>(enc, cb, out);
}

// round 15
// speedup vs baseline: 1.0320x; 1.0320x over previous
#include <cuda_runtime.h>
#include <cstdint>
#include <cstddef>

// VQ via warp-level mma.sync (tf32, 3-split). 512 threads: 8 point-slabs x 2 code-halves.
// dist_j = ||c_j||^2 - 2 x.c_j ; dot = hi.hi + hi.lo + lo.hi (tf32 mma, f32 accum).

#define N_PTS    16384
#define DIMS     64
#define K_CODES  8192
#define TM       128
#define TK       128
#define NTILES   (K_CODES / TK)    // 64
#define NTHREADS 512

#define STRIDE   70                          // floats per code row (bank-conflict-free)
#define SPLIT_F  (TK * STRIDE)               // floats per split per buffer (8960)
#define SM_CSQ   0                           // 2 x 128 f32
#define SM_FB    1024                        // 2 x 128 f32 (reduce dists)
#define SM_IB    2048                        // 2 x 128 i32 (reduce idx)
#define SM_B     3072
#define SMEM_BYTES (SM_B + 4 * SPLIT_F * 4)  // 146432

__device__ __align__(16) float g_csq[K_CODES];

// ---- csq precompute (exact fp32) ----
__global__ void __launch_bounds__(256) csq_kernel(const float* __restrict__ cb) {
    int i = blockIdx.x * blockDim.x + threadIdx.x;
    if (i >= K_CODES) return;
    const float4* row = reinterpret_cast<const float4*>(cb + (size_t)i * DIMS);
    float s = 0.f;
#pragma unroll
    for (int q = 0; q < DIMS / 4; q++) {
        float4 v = row[q];
        s += v.x * v.x + v.y * v.y + v.z * v.z + v.w * v.w;
    }
    g_csq[i] = s;
}

// ---- tf32 split ----
__device__ __forceinline__ void tf32_split(float x, uint32_t& hi, uint32_t& lo) {
    uint32_t h, l;
    asm("cvt.rna.tf32.f32 %0, %1;" : "=r"(h) : "f"(x));
    float r = x - __uint_as_float(h);
    asm("cvt.rna.tf32.f32 %0, %1;" : "=r"(l) : "f"(r));
    hi = h; lo = l;
}

__device__ __forceinline__ void mma8(float d[4], const uint32_t a[4],
                                     uint32_t b0, uint32_t b1) {
    asm("mma.sync.aligned.m16n8k8.row.col.f32.tf32.tf32.f32 "
        "{%0,%1,%2,%3}, {%4,%5,%6,%7}, {%8,%9}, {%0,%1,%2,%3};"
        : "+f"(d[0]), "+f"(d[1]), "+f"(d[2]), "+f"(d[3])
        : "r"(a[0]), "r"(a[1]), "r"(a[2]), "r"(a[3]), "r"(b0), "r"(b1));
}

// split 16 raw floats (dims q*16..q*16+15 of code c) into pair-interleaved hi/lo.
// slot(kk,t2,e) = kk*8 + t2*2 + e holds dim kk*8 + t2 + 4e. Stores: STS.64 conflict-free.
__device__ __forceinline__ void store_split(float* __restrict__ bh, float* __restrict__ bl,
                                            int c, int q, const float4 raw[4]) {
    const float* rf = reinterpret_cast<const float*>(raw);
    float* dh = bh + c * STRIDE + q * 16;
    float* dl = bl + c * STRIDE + q * 16;
#pragma unroll
    for (int f = 0; f < 2; f++) {
#pragma unroll
        for (int t2 = 0; t2 < 4; t2++) {
            uint2 h2, l2;
            tf32_split(rf[f * 8 + t2],     h2.x, l2.x);
            tf32_split(rf[f * 8 + t2 + 4], h2.y, l2.y);
            *reinterpret_cast<uint2*>(dh + f * 8 + t2 * 2) = h2;
            *reinterpret_cast<uint2*>(dl + f * 8 + t2 * 2) = l2;
        }
    }
}

// ---- main kernel -------------------------------------------------------------
__global__ void __launch_bounds__(NTHREADS, 1) vq_mma_kernel(
    const float* __restrict__ enc,
    const float* __restrict__ cb,
    float* __restrict__ out)
{
    extern __shared__ __align__(16) char smem[];
    float* csq_s = reinterpret_cast<float*>(smem + SM_CSQ);
    float* fb    = reinterpret_cast<float*>(smem + SM_FB);
    int*   ib    = reinterpret_cast<int*>(smem + SM_IB);
    float* sB    = reinterpret_cast<float*>(smem + SM_B);
#define BH(b) (sB + (size_t)(2 * (b)) * SPLIT_F)
#define BL(b) (sB + (size_t)(2 * (b) + 1) * SPLIT_F)

    const int tid  = threadIdx.x;
    const int lane = tid & 31;
    const int wid  = tid >> 5;
    const int gID  = lane >> 2;
    const int tig  = lane & 3;
    const int slab = wid & 7;     // 16-point slab
    const int ch   = wid >> 3;    // code half of the tile (0: 0-63, 1: 64-127)
    const int pbase = blockIdx.x * TM;

    const int cc = tid >> 2;      // code handled in load phase
    const int qq = tid & 3;       // 16-dim quarter

    // ---- A fragments: 16 points x 64 dims, tf32 hi/lo, register-resident ----
    uint32_t ah[8][4], al[8][4];
    {
        const float* e0 = enc + (size_t)(pbase + slab * 16 + gID) * DIMS;
        const float* e1 = e0 + 8 * DIMS;
#pragma unroll
        for (int kk = 0; kk < 8; kk++) {
            int k0 = kk * 8 + tig;
            tf32_split(e0[k0],     ah[kk][0], al[kk][0]);
            tf32_split(e1[k0],     ah[kk][1], al[kk][1]);
            tf32_split(e0[k0 + 4], ah[kk][2], al[kk][2]);
            tf32_split(e1[k0 + 4], ah[kk][3], al[kk][3]);
        }
    }

    // ---- tile 0 load + split ----
    {
        const float4* src = reinterpret_cast<const float4*>(cb + (size_t)cc * DIMS + qq * 16);
        float4 raw[4];
#pragma unroll
        for (int q = 0; q < 4; q++) raw[q] = src[q];
        store_split(BH(0), BL(0), cc, qq, raw);
        if (tid < 128) csq_s[tid] = g_csq[tid];
    }
    __syncthreads();

    float bd0 = 3.402823466e38f, bd1 = 3.402823466e38f;
    int   bi0 = 0, bi1 = 0;

    // per-thread read base (uint2 units): code n0 = ch*64 + gID, slot tig*2
    const int rbase = ((ch * 64 + gID) * STRIDE + tig * 2) >> 1;

#pragma unroll 1
    for (int t = 0; t < NTILES; t++) {
        const int buf = t & 1;
        const bool hasNext = (t + 1 < NTILES);

        // ---- stage next tile in registers (overlaps compute) ----
        float4 pf[4];
        float  pcs = 0.f;
        if (hasNext) {
            const float4* src = reinterpret_cast<const float4*>(
                cb + ((size_t)(t + 1) * TK + cc) * DIMS + qq * 16);
#pragma unroll
            for (int q = 0; q < 4; q++) pf[q] = src[q];
            if (tid < 128) pcs = g_csq[(t + 1) * TK + tid];
        }

        const uint2* bhp = reinterpret_cast<const uint2*>(BH(buf)) + rbase;
        const uint2* blp = reinterpret_cast<const uint2*>(BL(buf)) + rbase;
        const float* cst = csq_s + buf * 128;

#pragma unroll
        for (int jg = 0; jg < 2; jg++) {
            float d[4][4];
#pragma unroll
            for (int u = 0; u < 4; u++)
#pragma unroll
                for (int e = 0; e < 4; e++) d[u][e] = 0.f;

#pragma unroll
            for (int kk = 0; kk < 8; kk++) {
#pragma unroll
                for (int u = 0; u < 4; u++) {
                    const int off = (jg * 4 + u) * (8 * STRIDE / 2) + kk * 4;
                    uint2 h2 = bhp[off];
                    uint2 l2 = blp[off];
                    mma8(d[u], ah[kk], l2.x, l2.y);   // hi_a . lo_b
                    mma8(d[u], al[kk], h2.x, h2.y);   // lo_a . hi_b
                    mma8(d[u], ah[kk], h2.x, h2.y);   // hi_a . hi_b
                }
            }

            // ---- epilogue: dist = csq - 2*dot; ascending-index strict < ----
#pragma unroll
            for (int u = 0; u < 4; u++) {
                const int colb = ch * 64 + (jg * 4 + u) * 8 + 2 * tig;
                const int gidx = t * TK + colb;
                const float cs0 = cst[colb], cs1 = cst[colb + 1];
                float e00 = fmaf(-2.f, d[u][0], cs0);
                float e01 = fmaf(-2.f, d[u][1], cs1);
                float e10 = fmaf(-2.f, d[u][2], cs0);
                float e11 = fmaf(-2.f, d[u][3], cs1);
                if (e00 < bd0) { bd0 = e00; bi0 = gidx; }
                if (e01 < bd0) { bd0 = e01; bi0 = gidx + 1; }
                if (e10 < bd1) { bd1 = e10; bi1 = gidx; }
                if (e11 < bd1) { bd1 = e11; bi1 = gidx + 1; }
            }
        }

        // ---- split + store staged tile into other buffer ----
        if (hasNext) {
            const int nb = buf ^ 1;
            store_split(BH(nb), BL(nb), cc, qq, pf);
            if (tid < 128) csq_s[nb * 128 + tid] = pcs;
        }
        __syncthreads();
    }

    // ---- reduce across tig lanes (lexicographic: earliest index wins) ----
#pragma unroll
    for (int m = 1; m < 4; m <<= 1) {
        float od0 = __shfl_xor_sync(0xFFFFFFFFu, bd0, m);
        int   oi0 = __shfl_xor_sync(0xFFFFFFFFu, bi0, m);
        float od1 = __shfl_xor_sync(0xFFFFFFFFu, bd1, m);
        int   oi1 = __shfl_xor_sync(0xFFFFFFFFu, bi1, m);
        if (od0 < bd0 || (od0 == bd0 && oi0 < bi0)) { bd0 = od0; bi0 = oi0; }
        if (od1 < bd1 || (od1 == bd1 && oi1 < bi1)) { bd1 = od1; bi1 = oi1; }
    }
    if (tig == 0) {
        const int p = slab * 16 + gID;
        fb[ch * 128 + p]     = bd0; ib[ch * 128 + p]     = bi0;
        fb[ch * 128 + p + 8] = bd1; ib[ch * 128 + p + 8] = bi1;
    }
    __syncthreads();

    // ---- combine the two code halves per point ----
    if (tid < 128) {
        float d0 = fb[tid], d1 = fb[128 + tid];
        int   i0 = ib[tid], i1 = ib[128 + tid];
        ib[tid] = (d1 < d0 || (d1 == d0 && i1 < i0)) ? i1 : i0;
    }
    __syncthreads();

    // ---- gather: out[p] = codebook[argmin] (exact fp32 row copy) ----
    {
        const int ci = ib[cc];
        const float4* src = reinterpret_cast<const float4*>(cb + (size_t)ci * DIMS + qq * 16);
        float4* dst = reinterpret_cast<float4*>(out + (size_t)(pbase + cc) * DIMS + qq * 16);
#pragma unroll
        for (int q = 0; q < 4; q++) dst[q] = src[q];
    }
#undef BH
#undef BL
}

// ---- launcher ------------------------------------------------------------------
extern "C" void kernel_launch(void* const* d_in, const int* in_sizes, int n_in,
                              void* d_out, int out_size) {
    const float* enc = (const float*)d_in[0];
    const float* cb  = (const float*)d_in[1];
    float* out = (float*)d_out;

    static bool attr_set = false;
    if (!attr_set) {
        cudaFuncSetAttribute(vq_mma_kernel, cudaFuncAttributeMaxDynamicSharedMemorySize,
                             (int)SMEM_BYTES);
        attr_set = true;
    }

    csq_kernel<<<K_CODES / 256, 256>>>(cb);
    vq_mma_kernel<<<N_PTS / TM, NTHREADS, SMEM_BYTES>>>(enc, cb, out);
}

// round 16
// speedup vs baseline: 1.2129x; 1.1753x over previous
#include <cuda_runtime.h>
#include <cstdint>
#include <cstddef>

// VQ via warp-level mma.sync (tf32, 3-split). 256 threads: 4 slabs of 32 points x
// 2 code-halves; each B fragment feeds 6 MMAs (3 splits x 2 row-blocks).
// dist_j = ||c_j||^2 - 2 x.c_j ; dot = hi.hi + hi.lo + lo.hi (f32 accum).

#define N_PTS    16384
#define DIMS     64
#define K_CODES  8192
#define TM       128
#define TK       128
#define NTILES   (K_CODES / TK)    // 64
#define NTHREADS 256

#define STRIDE   72                          // floats per code row; 72 % 32 == 8 ->
                                             // LDS.64 banks 8g+2t+{0,1}: conflict-free
#define SPLIT_F  (TK * STRIDE)               // 9216 floats per split per buffer
#define SM_CSQ   0                           // 2 x 128 f32
#define SM_FB    1024                        // 2 x 128 f32
#define SM_IB    2048                        // 2 x 128 i32
#define SM_B     3072
#define SMEM_BYTES (SM_B + 4 * SPLIT_F * 4)  // 150528

__device__ __align__(16) float g_csq[K_CODES];

// ---- csq precompute (exact fp32) ----
__global__ void __launch_bounds__(256) csq_kernel(const float* __restrict__ cb) {
    int i = blockIdx.x * blockDim.x + threadIdx.x;
    if (i >= K_CODES) return;
    const float4* row = reinterpret_cast<const float4*>(cb + (size_t)i * DIMS);
    float s = 0.f;
#pragma unroll
    for (int q = 0; q < DIMS / 4; q++) {
        float4 v = row[q];
        s += v.x * v.x + v.y * v.y + v.z * v.z + v.w * v.w;
    }
    g_csq[i] = s;
}

// ---- tf32 split ----
__device__ __forceinline__ void tf32_split(float x, uint32_t& hi, uint32_t& lo) {
    uint32_t h, l;
    asm("cvt.rna.tf32.f32 %0, %1;" : "=r"(h) : "f"(x));
    float r = x - __uint_as_float(h);
    asm("cvt.rna.tf32.f32 %0, %1;" : "=r"(l) : "f"(r));
    hi = h; lo = l;
}

__device__ __forceinline__ void mma8(float d[4], const uint32_t a[4],
                                     uint32_t b0, uint32_t b1) {
    asm("mma.sync.aligned.m16n8k8.row.col.f32.tf32.tf32.f32 "
        "{%0,%1,%2,%3}, {%4,%5,%6,%7}, {%8,%9}, {%0,%1,%2,%3};"
        : "+f"(d[0]), "+f"(d[1]), "+f"(d[2]), "+f"(d[3])
        : "r"(a[0]), "r"(a[1]), "r"(a[2]), "r"(a[3]), "r"(b0), "r"(b1));
}

// split 32 raw floats (dims qh*32..+31 of code c) into pair-interleaved hi/lo.
// slot kk*8 + t2*2 + e holds dim kk*8 + t2 + 4e (uint2 per (t2) pair).
__device__ __forceinline__ void store_split(float* __restrict__ bh, float* __restrict__ bl,
                                            int c, int qh, const float4 raw[8]) {
    const float* rf = reinterpret_cast<const float*>(raw);
    float* dh = bh + c * STRIDE + qh * 32;
    float* dl = bl + c * STRIDE + qh * 32;
#pragma unroll
    for (int kl = 0; kl < 4; kl++) {
#pragma unroll
        for (int t2 = 0; t2 < 4; t2++) {
            uint2 h2, l2;
            tf32_split(rf[kl * 8 + t2],     h2.x, l2.x);
            tf32_split(rf[kl * 8 + t2 + 4], h2.y, l2.y);
            *reinterpret_cast<uint2*>(dh + kl * 8 + t2 * 2) = h2;
            *reinterpret_cast<uint2*>(dl + kl * 8 + t2 * 2) = l2;
        }
    }
}

// ---- main kernel -------------------------------------------------------------
__global__ void __launch_bounds__(NTHREADS, 1) vq_mma_kernel(
    const float* __restrict__ enc,
    const float* __restrict__ cb,
    float* __restrict__ out)
{
    extern __shared__ __align__(16) char smem[];
    float* csq_s = reinterpret_cast<float*>(smem + SM_CSQ);
    float* fb    = reinterpret_cast<float*>(smem + SM_FB);
    int*   ib    = reinterpret_cast<int*>(smem + SM_IB);
    float* sB    = reinterpret_cast<float*>(smem + SM_B);
#define BH(b) (sB + (size_t)(2 * (b)) * SPLIT_F)
#define BL(b) (sB + (size_t)(2 * (b) + 1) * SPLIT_F)

    const int tid  = threadIdx.x;
    const int lane = tid & 31;
    const int wid  = tid >> 5;
    const int gID  = lane >> 2;
    const int tig  = lane & 3;
    const int slab = wid & 3;     // 32-point slab
    const int ch   = wid >> 2;    // code half (0: codes 0-63, 1: 64-127)
    const int pbase = blockIdx.x * TM;

    const int cc = tid >> 1;      // staged code
    const int qh = tid & 1;       // staged 32-dim half

    // ---- A fragments: 32 points x 64 dims, tf32 hi/lo, two 16-row blocks ----
    uint32_t ah0[8][4], al0[8][4], ah1[8][4], al1[8][4];
    {
        const float* base = enc + (size_t)(pbase + slab * 32 + gID) * DIMS;
#pragma unroll
        for (int kk = 0; kk < 8; kk++) {
            int k0 = kk * 8 + tig;
            tf32_split(base[k0],                ah0[kk][0], al0[kk][0]);
            tf32_split(base[8 * DIMS + k0],     ah0[kk][1], al0[kk][1]);
            tf32_split(base[k0 + 4],            ah0[kk][2], al0[kk][2]);
            tf32_split(base[8 * DIMS + k0 + 4], ah0[kk][3], al0[kk][3]);
            tf32_split(base[16 * DIMS + k0],     ah1[kk][0], al1[kk][0]);
            tf32_split(base[24 * DIMS + k0],     ah1[kk][1], al1[kk][1]);
            tf32_split(base[16 * DIMS + k0 + 4], ah1[kk][2], al1[kk][2]);
            tf32_split(base[24 * DIMS + k0 + 4], ah1[kk][3], al1[kk][3]);
        }
    }

    // ---- tile 0 load + split ----
    {
        const float4* src = reinterpret_cast<const float4*>(cb + (size_t)cc * DIMS + qh * 32);
        float4 raw[8];
#pragma unroll
        for (int q = 0; q < 8; q++) raw[q] = src[q];
        store_split(BH(0), BL(0), cc, qh, raw);
        if (tid < 128) csq_s[tid] = g_csq[tid];
    }
    __syncthreads();

    float bd[4];
    int   bi[4];
#pragma unroll
    for (int s = 0; s < 4; s++) { bd[s] = 3.402823466e38f; bi[s] = 0; }

    // read base in uint2 units: code n = ch*64 + gID, slot tig*2
    const int rbase = (ch * 64 + gID) * (STRIDE / 2) + tig;

#pragma unroll 1
    for (int t = 0; t < NTILES; t++) {
        const int buf = t & 1;
        const bool hasNext = (t + 1 < NTILES);

        // ---- stage next tile in registers (overlaps compute) ----
        float4 pf[8];
        float  pcs = 0.f;
        if (hasNext) {
            const float4* src = reinterpret_cast<const float4*>(
                cb + ((size_t)(t + 1) * TK + cc) * DIMS + qh * 32);
#pragma unroll
            for (int q = 0; q < 8; q++) pf[q] = src[q];
            if (tid < 128) pcs = g_csq[(t + 1) * TK + tid];
        }

        const uint2* bhp = reinterpret_cast<const uint2*>(BH(buf)) + rbase;
        const uint2* blp = reinterpret_cast<const uint2*>(BL(buf)) + rbase;
        const float* cst = csq_s + buf * 128;

#pragma unroll
        for (int jg = 0; jg < 4; jg++) {
            float d[2][2][4];   // [row-block][u][frag]
#pragma unroll
            for (int r = 0; r < 2; r++)
#pragma unroll
                for (int u = 0; u < 2; u++)
#pragma unroll
                    for (int e = 0; e < 4; e++) d[r][u][e] = 0.f;

#pragma unroll
            for (int kk = 0; kk < 8; kk++) {
#pragma unroll
                for (int u = 0; u < 2; u++) {
                    const int off = (jg * 2 + u) * (8 * STRIDE / 2) + kk * 4;
                    uint2 h2 = bhp[off];
                    uint2 l2 = blp[off];
                    mma8(d[0][u], ah0[kk], l2.x, l2.y);   // hi_a . lo_b
                    mma8(d[1][u], ah1[kk], l2.x, l2.y);
                    mma8(d[0][u], al0[kk], h2.x, h2.y);   // lo_a . hi_b
                    mma8(d[1][u], al1[kk], h2.x, h2.y);
                    mma8(d[0][u], ah0[kk], h2.x, h2.y);   // hi_a . hi_b
                    mma8(d[1][u], ah1[kk], h2.x, h2.y);
                }
            }

            // ---- epilogue: dist = csq - 2*dot; ascending-index strict < ----
#pragma unroll
            for (int u = 0; u < 2; u++) {
                const int colb = ch * 64 + (jg * 2 + u) * 8 + 2 * tig;
                const int gidx = t * TK + colb;
                const float cs0 = cst[colb], cs1 = cst[colb + 1];
#pragma unroll
                for (int r = 0; r < 2; r++) {
                    float e00 = fmaf(-2.f, d[r][u][0], cs0);
                    float e01 = fmaf(-2.f, d[r][u][1], cs1);
                    float e10 = fmaf(-2.f, d[r][u][2], cs0);
                    float e11 = fmaf(-2.f, d[r][u][3], cs1);
                    const int s0 = r * 2, s1 = r * 2 + 1;
                    if (e00 < bd[s0]) { bd[s0] = e00; bi[s0] = gidx; }
                    if (e01 < bd[s0]) { bd[s0] = e01; bi[s0] = gidx + 1; }
                    if (e10 < bd[s1]) { bd[s1] = e10; bi[s1] = gidx; }
                    if (e11 < bd[s1]) { bd[s1] = e11; bi[s1] = gidx + 1; }
                }
            }
        }

        // ---- split + store staged tile into other buffer ----
        if (hasNext) {
            const int nb = buf ^ 1;
            store_split(BH(nb), BL(nb), cc, qh, pf);
            if (tid < 128) csq_s[nb * 128 + tid] = pcs;
        }
        __syncthreads();
    }

    // ---- reduce across tig lanes (lexicographic: earliest index wins) ----
#pragma unroll
    for (int m = 1; m < 4; m <<= 1) {
#pragma unroll
        for (int s = 0; s < 4; s++) {
            float od = __shfl_xor_sync(0xFFFFFFFFu, bd[s], m);
            int   oi = __shfl_xor_sync(0xFFFFFFFFu, bi[s], m);
            if (od < bd[s] || (od == bd[s] && oi < bi[s])) { bd[s] = od; bi[s] = oi; }
        }
    }
    if (tig == 0) {
#pragma unroll
        for (int s = 0; s < 4; s++) {
            const int p = slab * 32 + (s >> 1) * 16 + (s & 1) * 8 + gID;
            fb[ch * 128 + p] = bd[s];
            ib[ch * 128 + p] = bi[s];
        }
    }
    __syncthreads();

    // ---- combine the two code halves per point ----
    if (tid < 128) {
        float d0 = fb[tid], d1 = fb[128 + tid];
        int   i0 = ib[tid], i1 = ib[128 + tid];
        ib[tid] = (d1 < d0 || (d1 == d0 && i1 < i0)) ? i1 : i0;
    }
    __syncthreads();

    // ---- gather: out[p] = codebook[argmin] (exact fp32 row copy) ----
    {
        const int ci = ib[cc];
        const float4* src = reinterpret_cast<const float4*>(cb + (size_t)ci * DIMS + qh * 32);
        float4* dst = reinterpret_cast<float4*>(out + (size_t)(pbase + cc) * DIMS + qh * 32);
#pragma unroll
        for (int q = 0; q < 8; q++) dst[q] = src[q];
    }
#undef BH
#undef BL
}

// ---- launcher ------------------------------------------------------------------
extern "C" void kernel_launch(void* const* d_in, const int* in_sizes, int n_in,
                              void* d_out, int out_size) {
    const float* enc = (const float*)d_in[0];
    const float* cb  = (const float*)d_in[1];
    float* out = (float*)d_out;

    static bool attr_set = false;
    if (!attr_set) {
        cudaFuncSetAttribute(vq_mma_kernel, cudaFuncAttributeMaxDynamicSharedMemorySize,
                             (int)SMEM_BYTES);
        attr_set = true;
    }

    csq_kernel<<<K_CODES / 256, 256>>>(cb);
    vq_mma_kernel<<<N_PTS / TM, NTHREADS, SMEM_BYTES>>>(enc, cb, out);
}

// round 17
// speedup vs baseline: 1.2995x; 1.0714x over previous
#include <cuda_runtime.h>
#include <cstdint>
#include <cstddef>

// VQ via warp-level mma.sync (tf32, 3-split). 256 threads: 4 slabs of 32 points x
// 2 code-halves. Fused hi/lo B fragments (1 LDS.128 -> 6 MMAs), 8 accumulator
// chains per group. dist_j = ||c_j||^2 - 2 x.c_j ; dot = hi.hi + hi.lo + lo.hi.

#define N_PTS    16384
#define DIMS     64
#define K_CODES  8192
#define TM       128
#define TK       128
#define NTILES   (K_CODES / TK)    // 64
#define NTHREADS 256

#define CODE_CHUNKS 36                        // uint4 chunks per code row (576 B)
#define BUF_BYTES  (TK * CODE_CHUNKS * 16)    // 73728 per buffer
#define SM_CSQ 0                              // 2 x 128 f32
#define SM_FB  1024                           // 2 x 128 f32
#define SM_IB  2048                           // 2 x 128 i32
#define SM_B   3072
#define SMEM_BYTES (SM_B + 2 * BUF_BYTES)     // 150528

__device__ __align__(16) float g_csq[K_CODES];

// ---- csq precompute (exact fp32) ----
__global__ void __launch_bounds__(256) csq_kernel(const float* __restrict__ cb) {
    int i = blockIdx.x * blockDim.x + threadIdx.x;
    if (i >= K_CODES) return;
    const float4* row = reinterpret_cast<const float4*>(cb + (size_t)i * DIMS);
    float s = 0.f;
#pragma unroll
    for (int q = 0; q < DIMS / 4; q++) {
        float4 v = row[q];
        s += v.x * v.x + v.y * v.y + v.z * v.z + v.w * v.w;
    }
    g_csq[i] = s;
}

// ---- tf32 split ----
__device__ __forceinline__ void tf32_split(float x, uint32_t& hi, uint32_t& lo) {
    uint32_t h, l;
    asm("cvt.rna.tf32.f32 %0, %1;" : "=r"(h) : "f"(x));
    float r = x - __uint_as_float(h);
    asm("cvt.rna.tf32.f32 %0, %1;" : "=r"(l) : "f"(r));
    hi = h; lo = l;
}

__device__ __forceinline__ void mma8(float d[4], const uint32_t a[4],
                                     uint32_t b0, uint32_t b1) {
    asm("mma.sync.aligned.m16n8k8.row.col.f32.tf32.tf32.f32 "
        "{%0,%1,%2,%3}, {%4,%5,%6,%7}, {%8,%9}, {%0,%1,%2,%3};"
        : "+f"(d[0]), "+f"(d[1]), "+f"(d[2]), "+f"(d[3])
        : "r"(a[0]), "r"(a[1]), "r"(a[2]), "r"(a[3]), "r"(b0), "r"(b1));
}

// stage: thread (sc, tg) loads dims kk*8+tg and kk*8+tg+4 of one code (16 LDG.32)
__device__ __forceinline__ void load16(float raw[16], const float* __restrict__ base,
                                       int tg) {
#pragma unroll
    for (int kk = 0; kk < 8; kk++) {
        raw[kk * 2]     = base[kk * 8 + tg];
        raw[kk * 2 + 1] = base[kk * 8 + tg + 4];
    }
}

// split + store one code's 8 fused chunks: chunk(code,kk,tg) = {h0,h1,l0,l1}
__device__ __forceinline__ void split_store(char* __restrict__ bufbase, int code,
                                            int tg, const float raw[16]) {
    char* dst = bufbase + ((size_t)code * CODE_CHUNKS + tg) * 16;
#pragma unroll
    for (int kk = 0; kk < 8; kk++) {
        uint4 v;
        tf32_split(raw[kk * 2],     v.x, v.z);
        tf32_split(raw[kk * 2 + 1], v.y, v.w);
        *reinterpret_cast<uint4*>(dst + kk * 64) = v;
    }
}

// ---- main kernel -------------------------------------------------------------
__global__ void __launch_bounds__(NTHREADS, 1) vq_mma_kernel(
    const float* __restrict__ enc,
    const float* __restrict__ cb,
    float* __restrict__ out)
{
    extern __shared__ __align__(16) char smem[];
    float* csq_s = reinterpret_cast<float*>(smem + SM_CSQ);
    float* fb    = reinterpret_cast<float*>(smem + SM_FB);
    int*   ib    = reinterpret_cast<int*>(smem + SM_IB);
    char*  sB    = smem + SM_B;

    const int tid  = threadIdx.x;
    const int lane = tid & 31;
    const int wid  = tid >> 5;
    const int gID  = lane >> 2;
    const int tig  = lane & 3;
    const int slab = wid & 3;     // 32-point slab
    const int ch   = wid >> 2;    // code half (0: codes 0-63, 1: 64-127)
    const int pbase = blockIdx.x * TM;

    const int sc = tid >> 2;      // staged code low (0..63); also stages sc+64
    const int tg = tid & 3;       // staged tig

    // ---- A fragments: 32 points x 64 dims, tf32 hi/lo, two 16-row blocks ----
    uint32_t ah0[8][4], al0[8][4], ah1[8][4], al1[8][4];
    {
        const float* base = enc + (size_t)(pbase + slab * 32 + gID) * DIMS;
#pragma unroll
        for (int kk = 0; kk < 8; kk++) {
            int k0 = kk * 8 + tig;
            tf32_split(base[k0],                ah0[kk][0], al0[kk][0]);
            tf32_split(base[8 * DIMS + k0],     ah0[kk][1], al0[kk][1]);
            tf32_split(base[k0 + 4],            ah0[kk][2], al0[kk][2]);
            tf32_split(base[8 * DIMS + k0 + 4], ah0[kk][3], al0[kk][3]);
            tf32_split(base[16 * DIMS + k0],     ah1[kk][0], al1[kk][0]);
            tf32_split(base[24 * DIMS + k0],     ah1[kk][1], al1[kk][1]);
            tf32_split(base[16 * DIMS + k0 + 4], ah1[kk][2], al1[kk][2]);
            tf32_split(base[24 * DIMS + k0 + 4], al1[kk][3], al1[kk][3]);
        }
        // fix the typo above properly (ah1[kk][3]):
#pragma unroll
        for (int kk = 0; kk < 8; kk++) {
            int k0 = kk * 8 + tig;
            tf32_split(base[24 * DIMS + k0 + 4], ah1[kk][3], al1[kk][3]);
        }
    }

    // ---- tile 0: stage + split both codes ----
    {
        float raw[16];
        load16(raw, cb + (size_t)sc * DIMS, tg);
        split_store(sB, sc, tg, raw);
        load16(raw, cb + (size_t)(sc + 64) * DIMS, tg);
        split_store(sB, sc + 64, tg, raw);
        if (tid < 128) csq_s[tid] = g_csq[tid];
    }
    __syncthreads();

    float bd[4];
    int   bi[4];
#pragma unroll
    for (int s = 0; s < 4; s++) { bd[s] = 3.402823466e38f; bi[s] = 0; }

#pragma unroll 1
    for (int t = 0; t < NTILES; t++) {
        const int buf = t & 1;
        const bool hasNext = (t + 1 < NTILES);
        const char* bcur = sB + (size_t)buf * BUF_BYTES;
        char* bnxt = sB + (size_t)(buf ^ 1) * BUF_BYTES;
        const float* cst = csq_s + buf * 128;
        float pcs = 0.f;

#pragma unroll
        for (int jg = 0; jg < 2; jg++) {
            // ---- stage one code for tile t+1 (LDG latency hidden by MMAs) ----
            float raw[16];
            if (hasNext) {
                load16(raw, cb + ((size_t)(t + 1) * TK + sc + 64 * jg) * DIMS, tg);
                if (jg == 0 && tid < 128) pcs = g_csq[(t + 1) * TK + tid];
            }

            // ---- 8 accumulator chains: d[r][u] ----
            float d[2][4][4];
#pragma unroll
            for (int r = 0; r < 2; r++)
#pragma unroll
                for (int u = 0; u < 4; u++)
#pragma unroll
                    for (int e = 0; e < 4; e++) d[r][u][e] = 0.f;

            const char* rb = bcur +
                ((size_t)(ch * 64 + jg * 32 + gID) * CODE_CHUNKS + tig) * 16;

#pragma unroll
            for (int kk = 0; kk < 8; kk++) {
                uint4 f0 = *reinterpret_cast<const uint4*>(rb + kk * 64);
                uint4 f1 = *reinterpret_cast<const uint4*>(rb + kk * 64 + 8 * CODE_CHUNKS * 16);
                uint4 f2 = *reinterpret_cast<const uint4*>(rb + kk * 64 + 16 * CODE_CHUNKS * 16);
                uint4 f3 = *reinterpret_cast<const uint4*>(rb + kk * 64 + 24 * CODE_CHUNKS * 16);
                // split 0: hi_a . lo_b   (chain order: u-major, r inner -> distance 8)
                mma8(d[0][0], ah0[kk], f0.z, f0.w); mma8(d[1][0], ah1[kk], f0.z, f0.w);
                mma8(d[0][1], ah0[kk], f1.z, f1.w); mma8(d[1][1], ah1[kk], f1.z, f1.w);
                mma8(d[0][2], ah0[kk], f2.z, f2.w); mma8(d[1][2], ah1[kk], f2.z, f2.w);
                mma8(d[0][3], ah0[kk], f3.z, f3.w); mma8(d[1][3], ah1[kk], f3.z, f3.w);
                // split 1: lo_a . hi_b
                mma8(d[0][0], al0[kk], f0.x, f0.y); mma8(d[1][0], al1[kk], f0.x, f0.y);
                mma8(d[0][1], al0[kk], f1.x, f1.y); mma8(d[1][1], al1[kk], f1.x, f1.y);
                mma8(d[0][2], al0[kk], f2.x, f2.y); mma8(d[1][2], al1[kk], f2.x, f2.y);
                mma8(d[0][3], al0[kk], f3.x, f3.y); mma8(d[1][3], al1[kk], f3.x, f3.y);
                // split 2: hi_a . hi_b
                mma8(d[0][0], ah0[kk], f0.x, f0.y); mma8(d[1][0], ah1[kk], f0.x, f0.y);
                mma8(d[0][1], ah0[kk], f1.x, f1.y); mma8(d[1][1], ah1[kk], f1.x, f1.y);
                mma8(d[0][2], ah0[kk], f2.x, f2.y); mma8(d[1][2], ah1[kk], f2.x, f2.y);
                mma8(d[0][3], ah0[kk], f3.x, f3.y); mma8(d[1][3], ah1[kk], f3.x, f3.y);
            }

            // ---- epilogue: dist = csq - 2*dot; ascending-index strict < ----
#pragma unroll
            for (int u = 0; u < 4; u++) {
                const int colb = ch * 64 + jg * 32 + u * 8 + 2 * tig;
                const int gidx = t * TK + colb;
                const float cs0 = cst[colb], cs1 = cst[colb + 1];
#pragma unroll
                for (int r = 0; r < 2; r++) {
                    float e00 = fmaf(-2.f, d[r][u][0], cs0);
                    float e01 = fmaf(-2.f, d[r][u][1], cs1);
                    float e10 = fmaf(-2.f, d[r][u][2], cs0);
                    float e11 = fmaf(-2.f, d[r][u][3], cs1);
                    const int s0 = r * 2, s1 = r * 2 + 1;
                    if (e00 < bd[s0]) { bd[s0] = e00; bi[s0] = gidx; }
                    if (e01 < bd[s0]) { bd[s0] = e01; bi[s0] = gidx + 1; }
                    if (e10 < bd[s1]) { bd[s1] = e10; bi[s1] = gidx; }
                    if (e11 < bd[s1]) { bd[s1] = e11; bi[s1] = gidx + 1; }
                }
            }

            // ---- split + store the staged code into the other buffer ----
            if (hasNext) split_store(bnxt, sc + 64 * jg, tg, raw);
        }

        if (hasNext && tid < 128) csq_s[(buf ^ 1) * 128 + tid] = pcs;
        __syncthreads();
    }

    // ---- reduce across tig lanes (lexicographic: earliest index wins) ----
#pragma unroll
    for (int m = 1; m < 4; m <<= 1) {
#pragma unroll
        for (int s = 0; s < 4; s++) {
            float od = __shfl_xor_sync(0xFFFFFFFFu, bd[s], m);
            int   oi = __shfl_xor_sync(0xFFFFFFFFu, bi[s], m);
            if (od < bd[s] || (od == bd[s] && oi < bi[s])) { bd[s] = od; bi[s] = oi; }
        }
    }
    if (tig == 0) {
#pragma unroll
        for (int s = 0; s < 4; s++) {
            const int p = slab * 32 + (s >> 1) * 16 + (s & 1) * 8 + gID;
            fb[ch * 128 + p] = bd[s];
            ib[ch * 128 + p] = bi[s];
        }
    }
    __syncthreads();

    // ---- combine the two code halves per point ----
    if (tid < 128) {
        float d0 = fb[tid], d1 = fb[128 + tid];
        int   i0 = ib[tid], i1 = ib[128 + tid];
        ib[tid] = (d1 < d0 || (d1 == d0 && i1 < i0)) ? i1 : i0;
    }
    __syncthreads();

    // ---- gather: out[p] = codebook[argmin] (exact fp32 row copy) ----
    {
        const int cc = tid >> 1, qh = tid & 1;
        const int ci = ib[cc];
        const float4* src = reinterpret_cast<const float4*>(cb + (size_t)ci * DIMS + qh * 32);
        float4* dst = reinterpret_cast<float4*>(out + (size_t)(pbase + cc) * DIMS + qh * 32);
#pragma unroll
        for (int q = 0; q < 8; q++) dst[q] = src[q];
    }
}

// ---- launcher ------------------------------------------------------------------
extern "C" void kernel_launch(void* const* d_in, const int* in_sizes, int n_in,
                              void* d_out, int out_size) {
    const float* enc = (const float*)d_in[0];
    const float* cb  = (const float*)d_in[1];
    float* out = (float*)d_out;

    static bool attr_set = false;
    if (!attr_set) {
        cudaFuncSetAttribute(vq_mma_kernel, cudaFuncAttributeMaxDynamicSharedMemorySize,
                             (int)SMEM_BYTES);
        attr_set = true;
    }

    csq_kernel<<<K_CODES / 256, 256>>>(cb);
    vq_mma_kernel<<<N_PTS / TM, NTHREADS, SMEM_BYTES>>>(enc, cb, out);
}